// round 14
// baseline (speedup 1.0000x reference)
#include <cuda_runtime.h>
#include <cuda_bf16.h>
#include <math.h>
#include <stdint.h>

#define B_SZ   4
#define T_SEQ  1024
#define DIMC   768
#define NH     12
#define DH     64
#define NROWS  (B_SZ * T_SEQ)          // 4096
#define QKV_N  (3 * DIMC)              // 2304
#define KDIM   768

#define NEG_BIG (-3.0e38f)

// ============================================================================
// Scratch (static device globals; no allocation)
// ============================================================================
__device__ float g_qkv_c [(size_t)NROWS * QKV_N];
__device__ float g_qkv_ac[(size_t)NROWS * QKV_N];
__device__ float g_attn_c [(size_t)NROWS * DIMC];
__device__ float g_attn_ac[(size_t)NROWS * DIMC];
__device__ float g_proj_c [(size_t)NROWS * DIMC];
__device__ float g_proj_ac[(size_t)NROWS * DIMC];
__device__ float g_wtq_c [(size_t)QKV_N * KDIM];   // Wqkv_c^T  [2304][768]
__device__ float g_wtq_ac[(size_t)QKV_N * KDIM];
__device__ float g_wtp_c [(size_t)DIMC * KDIM];    // Wp_c^T    [768][768]
__device__ float g_wtp_ac[(size_t)DIMC * KDIM];

// ============================================================================
// helpers
// ============================================================================
__device__ __forceinline__ uint32_t smem_u32(const void* p) {
    uint32_t a;
    asm("{ .reg .u64 t; cvta.to.shared.u64 t, %1; cvt.u32.u64 %0, t; }" : "=r"(a) : "l"(p));
    return a;
}

__device__ __forceinline__ void cp16(uint32_t dst, const void* src) {
    asm volatile("cp.async.cg.shared.global [%0], [%1], 16;" :: "r"(dst), "l"(src));
}
#define CP_COMMIT() asm volatile("cp.async.commit_group;")

__device__ __forceinline__ uint32_t f32_to_tf32(float f) {
    uint32_t r;
    asm("cvt.rna.tf32.f32 %0, %1;" : "=r"(r) : "f"(f));
    return r;
}

__device__ __forceinline__ void mma_tf32(float& d0, float& d1, float& d2, float& d3,
                                         uint32_t a0, uint32_t a1, uint32_t a2, uint32_t a3,
                                         uint32_t b0, uint32_t b1) {
    asm volatile(
        "mma.sync.aligned.m16n8k8.row.col.f32.tf32.tf32.f32 "
        "{%0,%1,%2,%3}, {%4,%5,%6,%7}, {%8,%9}, {%0,%1,%2,%3};"
        : "+f"(d0), "+f"(d1), "+f"(d2), "+f"(d3)
        : "r"(a0), "r"(a1), "r"(a2), "r"(a3), "r"(b0), "r"(b1));
}

__device__ __forceinline__ void ldsm_x4(uint32_t& r0, uint32_t& r1, uint32_t& r2, uint32_t& r3,
                                        uint32_t addr) {
    asm volatile("ldmatrix.sync.aligned.m8n8.x4.shared.b16 {%0,%1,%2,%3}, [%4];"
                 : "=r"(r0), "=r"(r1), "=r"(r2), "=r"(r3) : "r"(addr));
}

// ============================================================================
// Per-branch weight transpose pair: z=0 -> (W0,T0,N=QKV_N), z=1 -> (W1,T1,DIMC)
// ============================================================================
__global__ void transpose_pair(const float* __restrict__ W0, float* __restrict__ T0,
                               const float* __restrict__ W1, float* __restrict__ T1)
{
    const int z = blockIdx.z;
    const int N = z ? DIMC : QKV_N;
    int nb = blockIdx.x * 32, kb = blockIdx.y * 32;
    if (nb >= N) return;
    const float* W = z ? W1 : W0;
    float*      Wt = z ? T1 : T0;

    __shared__ float t[32][33];
    int tx = threadIdx.x, ty = threadIdx.y;
#pragma unroll
    for (int i = 0; i < 4; i++)
        t[ty + i * 8][tx] = W[(size_t)(kb + ty + i * 8) * N + nb + tx];
    __syncthreads();
#pragma unroll
    for (int i = 0; i < 4; i++)
        Wt[(size_t)(nb + ty + i * 8) * KDIM + kb + tx] = t[tx][ty + i * 8];
}

// ============================================================================
// tf32 GEMM with ldmatrix fragments, BK=32 (proven).
// ============================================================================
#define BK 32
#define GSTG 3
#define RSTR 36

template<int BM_T, int BN_T>
__global__ void __launch_bounds__(256, 2) gemm_ldsm(
    const float* __restrict__ A,
    const float* __restrict__ Wt,
    const float* __restrict__ bias,
    float* __restrict__ C,
    int M, int N, int K)
{
    constexpr int A_STAGE = BM_T * RSTR;
    constexpr int B_STAGE = BN_T * RSTR;
    constexpr int STAGE   = A_STAGE + B_STAGE;
    constexpr int NT  = BN_T / 16;
    constexpr int NCH = (BM_T + BN_T) * 8;

    extern __shared__ float smf[];
    const uint32_t sbase = smem_u32(smf);

    const int tid  = threadIdx.x;
    const int lane = tid & 31;
    const int warp = tid >> 5;
    const int wm   = warp & 3;
    const int wn   = warp >> 2;
    const int lrow = lane >> 2;
    const int lcol = lane & 3;

    const int m0 = blockIdx.y * BM_T;
    const int n0 = blockIdx.x * BN_T;

    const int nk = K / BK;

    auto load_stage = [&](int s, int kb) {
        const int k0 = kb * BK;
        const uint32_t stB = sbase + (uint32_t)(s * STAGE) * 4;
#pragma unroll
        for (int i = 0; i < NCH / 256; i++) {
            int c = tid + i * 256;
            if (c < BM_T * 8) {
                int r = c >> 3, kc = (c & 7) * 4;
                cp16(stB + (uint32_t)(r * RSTR + kc) * 4,
                     &A[(size_t)(m0 + r) * K + k0 + kc]);
            } else {
                int c2 = c - BM_T * 8;
                int r = c2 >> 3, kc = (c2 & 7) * 4;
                cp16(stB + (uint32_t)(A_STAGE + r * RSTR + kc) * 4,
                     &Wt[(size_t)(n0 + r) * K + k0 + kc]);
            }
        }
        CP_COMMIT();
    };

    float acc[2][NT][4];
#pragma unroll
    for (int i = 0; i < 2; i++)
#pragma unroll
        for (int j = 0; j < NT; j++)
#pragma unroll
            for (int v = 0; v < 4; v++) acc[i][j][v] = 0.0f;

    const int a_lrow = (lane & 15);
    const int a_lcol = (lane >> 4) << 2;
    const int b_lrow = (lane & 7) + ((lane >> 4) << 3);
    const int b_lcol = ((lane >> 3) & 1) << 2;

    load_stage(0, 0);
    load_stage(1, 1);

    for (int kb = 0; kb < nk; kb++) {
        const int s = kb % GSTG;
        if (kb + 1 < nk) asm volatile("cp.async.wait_group 1;");
        else             asm volatile("cp.async.wait_group 0;");
        __syncthreads();

        if (kb + 2 < nk) load_stage((kb + 2) % GSTG, kb + 2);

        const uint32_t aB = sbase + (uint32_t)(s * STAGE) * 4;
        const uint32_t bB = aB + (uint32_t)A_STAGE * 4;

#pragma unroll
        for (int ks = 0; ks < 4; ks++) {
            const int kk = ks * 8;
            uint32_t af[2][4];
#pragma unroll
            for (int mt = 0; mt < 2; mt++) {
                uint32_t addr = aB +
                    (uint32_t)((wm * 32 + mt * 16 + a_lrow) * RSTR + kk + a_lcol) * 4;
                ldsm_x4(af[mt][0], af[mt][1], af[mt][2], af[mt][3], addr);
            }
#pragma unroll
            for (int j = 0; j < NT / 2; j++) {
                uint32_t b0, b1, b2, b3;
                uint32_t addr = bB +
                    (uint32_t)((wn * (BN_T / 2) + j * 16 + b_lrow) * RSTR + kk + b_lcol) * 4;
                ldsm_x4(b0, b1, b2, b3, addr);
#pragma unroll
                for (int mt = 0; mt < 2; mt++) {
                    mma_tf32(acc[mt][2*j][0], acc[mt][2*j][1], acc[mt][2*j][2], acc[mt][2*j][3],
                             af[mt][0], af[mt][1], af[mt][2], af[mt][3], b0, b1);
                    mma_tf32(acc[mt][2*j+1][0], acc[mt][2*j+1][1], acc[mt][2*j+1][2], acc[mt][2*j+1][3],
                             af[mt][0], af[mt][1], af[mt][2], af[mt][3], b2, b3);
                }
            }
        }
    }

#pragma unroll
    for (int mt = 0; mt < 2; mt++) {
        int r = m0 + wm * 32 + mt * 16 + lrow;
#pragma unroll
        for (int nt = 0; nt < NT; nt++) {
            int c = n0 + wn * (BN_T / 2) + nt * 8 + lcol * 2;
            float2 bv = *(const float2*)&bias[c];
            float2 o0, o1;
            o0.x = acc[mt][nt][0] + bv.x;
            o0.y = acc[mt][nt][1] + bv.y;
            o1.x = acc[mt][nt][2] + bv.x;
            o1.y = acc[mt][nt][3] + bv.y;
            *(float2*)&C[(size_t)r * N + c]       = o0;
            *(float2*)&C[(size_t)(r + 8) * N + c] = o1;
        }
    }
}

// ============================================================================
// Tensor-core flash attention (proven: ldmatrix + no online max).
// ============================================================================
#define AT_BM 64
#define AT_BN 64
#define ASTRD 68
#define AT_SMEM (3 * 64 * ASTRD * 4)   // 52224 B

__global__ void __launch_bounds__(128) attn_mma(
    const float* __restrict__ qkv, float* __restrict__ outp, int causal)
{
    extern __shared__ uint32_t asmem[];
    uint32_t* Ks = asmem;                  // [64][68]
    uint32_t* Vt = Ks + 64 * ASTRD;        // [64 d][68 key]
    uint32_t* Ps = Vt + 64 * ASTRD;        // [64][68]
    const uint32_t sK = smem_u32(Ks);
    const uint32_t sV = smem_u32(Vt);
    const uint32_t sP = smem_u32(Ps);

    const int b  = blockIdx.z;
    const int h  = blockIdx.y;
    const int m0 = (causal ? (gridDim.x - 1 - blockIdx.x) : blockIdx.x) * AT_BM;

    const int tid  = threadIdx.x;
    const int warp = tid >> 5;
    const int lane = tid & 31;
    const int lrow = lane >> 2;
    const int lcol = lane & 3;
    const int a_lrow = (lane & 15);
    const int a_lcol = (lane >> 4) << 2;
    const int b_lrow = (lane & 7) + ((lane >> 4) << 3);
    const int b_lcol = ((lane >> 3) & 1) << 2;

    const float* qbase = qkv + (size_t)b * T_SEQ * QKV_N + h * DH;
    const float* kbase = qbase + DIMC;
    const float* vbase = qbase + 2 * DIMC;

#pragma unroll
    for (int i = 0; i < 8; i++) {
        int idx = i * 128 + tid;
        int r = idx >> 4, c4 = (idx & 15) * 4;
        *(uint4*)&Ps[r * ASTRD + c4] =
            *(const uint4*)&qbase[(size_t)(m0 + r) * QKV_N + c4];
    }
    __syncthreads();

    uint32_t qa[8][4];
    {
        const float* Pf = (const float*)Ps;
        const int r0 = (warp * 16 + lrow) * ASTRD;
        const int r1 = r0 + 8 * ASTRD;
#pragma unroll
        for (int kt = 0; kt < 8; kt++) {
            int c = kt * 8 + lcol;
            qa[kt][0] = f32_to_tf32(Pf[r0 + c]     * 0.125f);
            qa[kt][1] = f32_to_tf32(Pf[r1 + c]     * 0.125f);
            qa[kt][2] = f32_to_tf32(Pf[r0 + c + 4] * 0.125f);
            qa[kt][3] = f32_to_tf32(Pf[r1 + c + 4] * 0.125f);
        }
    }
    __syncthreads();

    float o[8][4];
#pragma unroll
    for (int i = 0; i < 8; i++)
#pragma unroll
        for (int j = 0; j < 4; j++) o[i][j] = 0.0f;
    float l0 = 0.0f, l1 = 0.0f;

    const int r0g = m0 + warp * 16 + lrow;
    const int r1g = r0g + 8;

    const int n_start = causal ? 0 : m0;
    const int n_end   = causal ? (m0 + AT_BM) : T_SEQ;

    for (int n0 = n_start; n0 < n_end; n0 += AT_BN) {
#pragma unroll
        for (int i = 0; i < 8; i++) {
            int idx = i * 128 + tid;
            int r = idx >> 4, c4 = (idx & 15) * 4;
            *(uint4*)&Ks[r * ASTRD + c4] =
                *(const uint4*)&kbase[(size_t)(n0 + r) * QKV_N + c4];
        }
#pragma unroll
        for (int i = 0; i < 8; i++) {
            int idx = i * 128 + tid;
            int d  = idx & 63;
            int kg = idx >> 6;
            uint4 v;
            v.x = __float_as_uint(vbase[(size_t)(n0 + kg * 4 + 0) * QKV_N + d]);
            v.y = __float_as_uint(vbase[(size_t)(n0 + kg * 4 + 1) * QKV_N + d]);
            v.z = __float_as_uint(vbase[(size_t)(n0 + kg * 4 + 2) * QKV_N + d]);
            v.w = __float_as_uint(vbase[(size_t)(n0 + kg * 4 + 3) * QKV_N + d]);
            *(uint4*)&Vt[d * ASTRD + kg * 4] = v;
        }
        __syncthreads();

        // ---- S = Q K^T ----
        float s[8][4];
#pragma unroll
        for (int nt = 0; nt < 8; nt++)
            s[nt][0] = s[nt][1] = s[nt][2] = s[nt][3] = 0.0f;
#pragma unroll
        for (int kt = 0; kt < 8; kt++) {
#pragma unroll
            for (int j = 0; j < 4; j++) {
                uint32_t b0, b1, b2, b3;
                uint32_t addr = sK +
                    (uint32_t)((j * 16 + b_lrow) * ASTRD + kt * 8 + b_lcol) * 4;
                ldsm_x4(b0, b1, b2, b3, addr);
                mma_tf32(s[2*j][0], s[2*j][1], s[2*j][2], s[2*j][3],
                         qa[kt][0], qa[kt][1], qa[kt][2], qa[kt][3], b0, b1);
                mma_tf32(s[2*j+1][0], s[2*j+1][1], s[2*j+1][2], s[2*j+1][3],
                         qa[kt][0], qa[kt][1], qa[kt][2], qa[kt][3], b2, b3);
            }
        }

        const bool need_mask = causal ? (n0 + AT_BN - 1 > m0 + warp * 16)
                                      : (n0 < m0 + warp * 16 + 15);
        if (need_mask) {
#pragma unroll
            for (int nt = 0; nt < 8; nt++) {
                int c0 = n0 + nt * 8 + 2 * lcol;
                int c1 = c0 + 1;
                if (causal) {
                    if (c0 > r0g) s[nt][0] = NEG_BIG;
                    if (c1 > r0g) s[nt][1] = NEG_BIG;
                    if (c0 > r1g) s[nt][2] = NEG_BIG;
                    if (c1 > r1g) s[nt][3] = NEG_BIG;
                } else {
                    if (c0 < r0g) s[nt][0] = NEG_BIG;
                    if (c1 < r0g) s[nt][1] = NEG_BIG;
                    if (c0 < r1g) s[nt][2] = NEG_BIG;
                    if (c1 < r1g) s[nt][3] = NEG_BIG;
                }
            }
        }

        // ---- exp + per-thread partial sums ----
#pragma unroll
        for (int nt = 0; nt < 8; nt++) {
            s[nt][0] = __expf(s[nt][0]); l0 += s[nt][0];
            s[nt][1] = __expf(s[nt][1]); l0 += s[nt][1];
            s[nt][2] = __expf(s[nt][2]); l1 += s[nt][2];
            s[nt][3] = __expf(s[nt][3]); l1 += s[nt][3];
        }

        // ---- P -> smem (warp-private rows, raw bits) ----
        {
            const int pr0 = (warp * 16 + lrow) * ASTRD;
            const int pr1 = pr0 + 8 * ASTRD;
#pragma unroll
            for (int nt = 0; nt < 8; nt++) {
                int c = nt * 8 + 2 * lcol;
                Ps[pr0 + c]     = __float_as_uint(s[nt][0]);
                Ps[pr0 + c + 1] = __float_as_uint(s[nt][1]);
                Ps[pr1 + c]     = __float_as_uint(s[nt][2]);
                Ps[pr1 + c + 1] = __float_as_uint(s[nt][3]);
            }
        }
        __syncwarp();

        // ---- O += P @ V ----
#pragma unroll
        for (int kt = 0; kt < 8; kt++) {
            uint32_t a0, a1, a2, a3;
            uint32_t aaddr = sP +
                (uint32_t)((warp * 16 + a_lrow) * ASTRD + kt * 8 + a_lcol) * 4;
            ldsm_x4(a0, a1, a2, a3, aaddr);
#pragma unroll
            for (int j = 0; j < 4; j++) {
                uint32_t b0, b1, b2, b3;
                uint32_t baddr = sV +
                    (uint32_t)((j * 16 + b_lrow) * ASTRD + kt * 8 + b_lcol) * 4;
                ldsm_x4(b0, b1, b2, b3, baddr);
                mma_tf32(o[2*j][0], o[2*j][1], o[2*j][2], o[2*j][3],
                         a0, a1, a2, a3, b0, b1);
                mma_tf32(o[2*j+1][0], o[2*j+1][1], o[2*j+1][2], o[2*j+1][3],
                         a0, a1, a2, a3, b2, b3);
            }
        }
        __syncthreads();
    }

    l0 += __shfl_xor_sync(0xffffffff, l0, 1);
    l0 += __shfl_xor_sync(0xffffffff, l0, 2);
    l1 += __shfl_xor_sync(0xffffffff, l1, 1);
    l1 += __shfl_xor_sync(0xffffffff, l1, 2);

    float inv0 = 1.0f / l0, inv1 = 1.0f / l1;
    size_t ob = (size_t)(b * T_SEQ + r0g) * DIMC + h * DH;
#pragma unroll
    for (int nt = 0; nt < 8; nt++) {
        int c = nt * 8 + 2 * lcol;
        float2 w0, w1;
        w0.x = o[nt][0] * inv0; w0.y = o[nt][1] * inv0;
        w1.x = o[nt][2] * inv1; w1.y = o[nt][3] * inv1;
        *(float2*)&outp[ob + c]            = w0;
        *(float2*)&outp[ob + 8 * DIMC + c] = w1;
    }
}

// ============================================================================
// Fused residual + LayerNorm (proven)
// ============================================================================
__global__ void residual_ln(const float* __restrict__ x,
                            const float* __restrict__ pc,
                            const float* __restrict__ pac,
                            const float* __restrict__ gamma,
                            const float* __restrict__ beta,
                            float* __restrict__ out)
{
    const int row = blockIdx.x;
    const size_t base = (size_t)row * DIMC;
    const int t = threadIdx.x;

    __shared__ float red[256];

    float y[3];
    float s = 0.0f;
#pragma unroll
    for (int i = 0; i < 3; i++) {
        int c = t + i * 256;
        y[i] = x[base + c] + pc[base + c] + pac[base + c];
        s += y[i];
    }
    red[t] = s;
    __syncthreads();
    for (int off = 128; off > 0; off >>= 1) {
        if (t < off) red[t] += red[t + off];
        __syncthreads();
    }
    float mu = red[0] * (1.0f / DIMC);
    __syncthreads();

    float vs = 0.0f;
#pragma unroll
    for (int i = 0; i < 3; i++) {
        float d = y[i] - mu;
        vs += d * d;
    }
    red[t] = vs;
    __syncthreads();
    for (int off = 128; off > 0; off >>= 1) {
        if (t < off) red[t] += red[t + off];
        __syncthreads();
    }
    float inv = rsqrtf(red[0] * (1.0f / DIMC) + 1e-5f);

#pragma unroll
    for (int i = 0; i < 3; i++) {
        int c = t + i * 256;
        out[base + c] = (y[i] - mu) * inv * gamma[c] + beta[c];
    }
}

// ============================================================================
// launch — staggered two-stream pipeline:
//   s1: transpose(c) -> QKV_c ----------------> attn_c -> proj_c
//   s2: transpose(ac) -> [wait QKV_c] QKV_ac -> attn_ac -> proj_ac
// so tensor-bound GEMMs overlap MUFU/LSU-bound attention, never each other.
// ============================================================================
#define GEMM_SMEM(BM_T, BN_T) ((GSTG * ((BM_T) + (BN_T)) * RSTR) * 4)

extern "C" void kernel_launch(void* const* d_in, const int* in_sizes, int n_in,
                              void* d_out, int out_size)
{
    const float* x       = (const float*)d_in[0];
    const float* Wqkv_c  = (const float*)d_in[1];
    const float* bqkv_c  = (const float*)d_in[2];
    const float* Wp_c    = (const float*)d_in[3];
    const float* bp_c    = (const float*)d_in[4];
    const float* Wqkv_ac = (const float*)d_in[5];
    const float* bqkv_ac = (const float*)d_in[6];
    const float* Wp_ac   = (const float*)d_in[7];
    const float* bp_ac   = (const float*)d_in[8];
    const float* gamma   = (const float*)d_in[9];
    const float* beta    = (const float*)d_in[10];
    float* out = (float*)d_out;

    float *qkv_c, *qkv_ac, *attn_c, *attn_ac, *proj_c, *proj_ac;
    float *wtq_c, *wtq_ac, *wtp_c, *wtp_ac;
    cudaGetSymbolAddress((void**)&qkv_c,  g_qkv_c);
    cudaGetSymbolAddress((void**)&qkv_ac, g_qkv_ac);
    cudaGetSymbolAddress((void**)&attn_c,  g_attn_c);
    cudaGetSymbolAddress((void**)&attn_ac, g_attn_ac);
    cudaGetSymbolAddress((void**)&proj_c,  g_proj_c);
    cudaGetSymbolAddress((void**)&proj_ac, g_proj_ac);
    cudaGetSymbolAddress((void**)&wtq_c,  g_wtq_c);
    cudaGetSymbolAddress((void**)&wtq_ac, g_wtq_ac);
    cudaGetSymbolAddress((void**)&wtp_c,  g_wtp_c);
    cudaGetSymbolAddress((void**)&wtp_ac, g_wtp_ac);

    static cudaStream_t s1 = nullptr, s2 = nullptr;
    static cudaEvent_t ev0, ev1, ev2, ev3;
    if (!s1) {
        cudaStreamCreateWithFlags(&s1, cudaStreamNonBlocking);
        cudaStreamCreateWithFlags(&s2, cudaStreamNonBlocking);
        cudaEventCreateWithFlags(&ev0, cudaEventDisableTiming);
        cudaEventCreateWithFlags(&ev1, cudaEventDisableTiming);
        cudaEventCreateWithFlags(&ev2, cudaEventDisableTiming);
        cudaEventCreateWithFlags(&ev3, cudaEventDisableTiming);
        cudaFuncSetAttribute((const void*)gemm_ldsm<128,128>,
                             cudaFuncAttributeMaxDynamicSharedMemorySize, GEMM_SMEM(128,128));
        cudaFuncSetAttribute((const void*)attn_mma,
                             cudaFuncAttributeMaxDynamicSharedMemorySize, AT_SMEM);
    }

    dim3 blk256(256);
    dim3 tgrid(QKV_N / 32, KDIM / 32, 2);
    dim3 tblk(32, 8);

    // ---- fork ----
    cudaEventRecord(ev0, 0);
    cudaStreamWaitEvent(s1, ev0, 0);
    cudaStreamWaitEvent(s2, ev0, 0);

    // ---- branch c on s1 ----
    transpose_pair<<<tgrid, tblk, 0, s1>>>(Wqkv_c, wtq_c, Wp_c, wtp_c);
    gemm_ldsm<128,128><<<dim3(QKV_N / 128, NROWS / 128, 1), blk256,
                         GEMM_SMEM(128,128), s1>>>(
        x, wtq_c, bqkv_c, qkv_c, NROWS, QKV_N, KDIM);
    cudaEventRecord(ev3, s1);          // QKV_c done -> release s2's QKV
    attn_mma<<<dim3(T_SEQ / AT_BM, NH, B_SZ), dim3(128), AT_SMEM, s1>>>(
        qkv_c, attn_c, 1);
    gemm_ldsm<128,128><<<dim3(DIMC / 128, NROWS / 128, 1), blk256,
                         GEMM_SMEM(128,128), s1>>>(
        attn_c, wtp_c, bp_c, proj_c, NROWS, DIMC, KDIM);

    // ---- branch ac on s2 (QKV staggered behind QKV_c) ----
    transpose_pair<<<tgrid, tblk, 0, s2>>>(Wqkv_ac, wtq_ac, Wp_ac, wtp_ac);
    cudaStreamWaitEvent(s2, ev3, 0);
    gemm_ldsm<128,128><<<dim3(QKV_N / 128, NROWS / 128, 1), blk256,
                         GEMM_SMEM(128,128), s2>>>(
        x, wtq_ac, bqkv_ac, qkv_ac, NROWS, QKV_N, KDIM);
    attn_mma<<<dim3(T_SEQ / AT_BM, NH, B_SZ), dim3(128), AT_SMEM, s2>>>(
        qkv_ac, attn_ac, 0);
    gemm_ldsm<128,128><<<dim3(DIMC / 128, NROWS / 128, 1), blk256,
                         GEMM_SMEM(128,128), s2>>>(
        attn_ac, wtp_ac, bp_ac, proj_ac, NROWS, DIMC, KDIM);

    // ---- join ----
    cudaEventRecord(ev1, s1);
    cudaEventRecord(ev2, s2);
    cudaStreamWaitEvent(0, ev1, 0);
    cudaStreamWaitEvent(0, ev2, 0);

    // ---- fused residual + layernorm ----
    residual_ln<<<NROWS, blk256>>>(x, proj_c, proj_ac, gamma, beta, out);
}

// round 15
// speedup vs baseline: 1.0936x; 1.0936x over previous
#include <cuda_runtime.h>
#include <cuda_bf16.h>
#include <math.h>
#include <stdint.h>

#define B_SZ   4
#define T_SEQ  1024
#define DIMC   768
#define NH     12
#define DH     64
#define NROWS  (B_SZ * T_SEQ)          // 4096
#define QKV_N  (3 * DIMC)              // 2304
#define KDIM   768

#define NEG_BIG (-3.0e38f)

// ============================================================================
// Scratch (static device globals; no allocation)
// ============================================================================
__device__ float g_qkv_c [(size_t)NROWS * QKV_N];
__device__ float g_qkv_ac[(size_t)NROWS * QKV_N];
__device__ float g_attn_c [(size_t)NROWS * DIMC];
__device__ float g_attn_ac[(size_t)NROWS * DIMC];
__device__ float g_proj_c [(size_t)NROWS * DIMC];
__device__ float g_proj_ac[(size_t)NROWS * DIMC];
__device__ float g_wtq_c [(size_t)QKV_N * KDIM];   // Wqkv_c^T  [2304][768]
__device__ float g_wtq_ac[(size_t)QKV_N * KDIM];
__device__ float g_wtp_c [(size_t)DIMC * KDIM];    // Wp_c^T    [768][768]
__device__ float g_wtp_ac[(size_t)DIMC * KDIM];

// ============================================================================
// helpers
// ============================================================================
__device__ __forceinline__ uint32_t smem_u32(const void* p) {
    uint32_t a;
    asm("{ .reg .u64 t; cvta.to.shared.u64 t, %1; cvt.u32.u64 %0, t; }" : "=r"(a) : "l"(p));
    return a;
}

__device__ __forceinline__ void cp16(uint32_t dst, const void* src) {
    asm volatile("cp.async.cg.shared.global [%0], [%1], 16;" :: "r"(dst), "l"(src));
}
#define CP_COMMIT() asm volatile("cp.async.commit_group;")

__device__ __forceinline__ uint32_t f32_to_tf32(float f) {
    uint32_t r;
    asm("cvt.rna.tf32.f32 %0, %1;" : "=r"(r) : "f"(f));
    return r;
}

__device__ __forceinline__ void mma_tf32(float& d0, float& d1, float& d2, float& d3,
                                         uint32_t a0, uint32_t a1, uint32_t a2, uint32_t a3,
                                         uint32_t b0, uint32_t b1) {
    asm volatile(
        "mma.sync.aligned.m16n8k8.row.col.f32.tf32.tf32.f32 "
        "{%0,%1,%2,%3}, {%4,%5,%6,%7}, {%8,%9}, {%0,%1,%2,%3};"
        : "+f"(d0), "+f"(d1), "+f"(d2), "+f"(d3)
        : "r"(a0), "r"(a1), "r"(a2), "r"(a3), "r"(b0), "r"(b1));
}

__device__ __forceinline__ void ldsm_x4(uint32_t& r0, uint32_t& r1, uint32_t& r2, uint32_t& r3,
                                        uint32_t addr) {
    asm volatile("ldmatrix.sync.aligned.m8n8.x4.shared.b16 {%0,%1,%2,%3}, [%4];"
                 : "=r"(r0), "=r"(r1), "=r"(r2), "=r"(r3) : "r"(addr));
}

// ============================================================================
// Batched weight transpose: z selects (W, Wt, N); K=768 rows always.
// ============================================================================
__global__ void transpose_all(const float* __restrict__ W0, float* __restrict__ T0,
                              const float* __restrict__ W1, float* __restrict__ T1,
                              const float* __restrict__ W2, float* __restrict__ T2,
                              const float* __restrict__ W3, float* __restrict__ T3)
{
    const int z = blockIdx.z;
    const int N = (z < 2) ? QKV_N : DIMC;
    int nb = blockIdx.x * 32, kb = blockIdx.y * 32;
    if (nb >= N) return;
    const float* W = (z == 0) ? W0 : (z == 1) ? W1 : (z == 2) ? W2 : W3;
    float*      Wt = (z == 0) ? T0 : (z == 1) ? T1 : (z == 2) ? T2 : T3;

    __shared__ float t[32][33];
    int tx = threadIdx.x, ty = threadIdx.y;
#pragma unroll
    for (int i = 0; i < 4; i++)
        t[ty + i * 8][tx] = W[(size_t)(kb + ty + i * 8) * N + nb + tx];
    __syncthreads();
#pragma unroll
    for (int i = 0; i < 4; i++)
        Wt[(size_t)(nb + ty + i * 8) * KDIM + kb + tx] = t[tx][ty + i * 8];
}

// ============================================================================
// tf32 GEMM with ldmatrix fragments, BK=32 (proven).
// ============================================================================
#define BK 32
#define GSTG 3
#define RSTR 36

template<int BM_T, int BN_T>
__global__ void __launch_bounds__(256, 2) gemm_ldsm(
    const float* __restrict__ A,
    const float* __restrict__ Wt,
    const float* __restrict__ bias,
    float* __restrict__ C,
    int M, int N, int K)
{
    constexpr int A_STAGE = BM_T * RSTR;
    constexpr int B_STAGE = BN_T * RSTR;
    constexpr int STAGE   = A_STAGE + B_STAGE;
    constexpr int NT  = BN_T / 16;
    constexpr int NCH = (BM_T + BN_T) * 8;

    extern __shared__ float smf[];
    const uint32_t sbase = smem_u32(smf);

    const int tid  = threadIdx.x;
    const int lane = tid & 31;
    const int warp = tid >> 5;
    const int wm   = warp & 3;
    const int wn   = warp >> 2;
    const int lrow = lane >> 2;
    const int lcol = lane & 3;

    const int m0 = blockIdx.y * BM_T;
    const int n0 = blockIdx.x * BN_T;

    const int nk = K / BK;

    auto load_stage = [&](int s, int kb) {
        const int k0 = kb * BK;
        const uint32_t stB = sbase + (uint32_t)(s * STAGE) * 4;
#pragma unroll
        for (int i = 0; i < NCH / 256; i++) {
            int c = tid + i * 256;
            if (c < BM_T * 8) {
                int r = c >> 3, kc = (c & 7) * 4;
                cp16(stB + (uint32_t)(r * RSTR + kc) * 4,
                     &A[(size_t)(m0 + r) * K + k0 + kc]);
            } else {
                int c2 = c - BM_T * 8;
                int r = c2 >> 3, kc = (c2 & 7) * 4;
                cp16(stB + (uint32_t)(A_STAGE + r * RSTR + kc) * 4,
                     &Wt[(size_t)(n0 + r) * K + k0 + kc]);
            }
        }
        CP_COMMIT();
    };

    float acc[2][NT][4];
#pragma unroll
    for (int i = 0; i < 2; i++)
#pragma unroll
        for (int j = 0; j < NT; j++)
#pragma unroll
            for (int v = 0; v < 4; v++) acc[i][j][v] = 0.0f;

    const int a_lrow = (lane & 15);
    const int a_lcol = (lane >> 4) << 2;
    const int b_lrow = (lane & 7) + ((lane >> 4) << 3);
    const int b_lcol = ((lane >> 3) & 1) << 2;

    load_stage(0, 0);
    load_stage(1, 1);

    for (int kb = 0; kb < nk; kb++) {
        const int s = kb % GSTG;
        if (kb + 1 < nk) asm volatile("cp.async.wait_group 1;");
        else             asm volatile("cp.async.wait_group 0;");
        __syncthreads();

        if (kb + 2 < nk) load_stage((kb + 2) % GSTG, kb + 2);

        const uint32_t aB = sbase + (uint32_t)(s * STAGE) * 4;
        const uint32_t bB = aB + (uint32_t)A_STAGE * 4;

#pragma unroll
        for (int ks = 0; ks < 4; ks++) {
            const int kk = ks * 8;
            uint32_t af[2][4];
#pragma unroll
            for (int mt = 0; mt < 2; mt++) {
                uint32_t addr = aB +
                    (uint32_t)((wm * 32 + mt * 16 + a_lrow) * RSTR + kk + a_lcol) * 4;
                ldsm_x4(af[mt][0], af[mt][1], af[mt][2], af[mt][3], addr);
            }
#pragma unroll
            for (int j = 0; j < NT / 2; j++) {
                uint32_t b0, b1, b2, b3;
                uint32_t addr = bB +
                    (uint32_t)((wn * (BN_T / 2) + j * 16 + b_lrow) * RSTR + kk + b_lcol) * 4;
                ldsm_x4(b0, b1, b2, b3, addr);
#pragma unroll
                for (int mt = 0; mt < 2; mt++) {
                    mma_tf32(acc[mt][2*j][0], acc[mt][2*j][1], acc[mt][2*j][2], acc[mt][2*j][3],
                             af[mt][0], af[mt][1], af[mt][2], af[mt][3], b0, b1);
                    mma_tf32(acc[mt][2*j+1][0], acc[mt][2*j+1][1], acc[mt][2*j+1][2], acc[mt][2*j+1][3],
                             af[mt][0], af[mt][1], af[mt][2], af[mt][3], b2, b3);
                }
            }
        }
    }

#pragma unroll
    for (int mt = 0; mt < 2; mt++) {
        int r = m0 + wm * 32 + mt * 16 + lrow;
#pragma unroll
        for (int nt = 0; nt < NT; nt++) {
            int c = n0 + wn * (BN_T / 2) + nt * 8 + lcol * 2;
            float2 bv = *(const float2*)&bias[c];
            float2 o0, o1;
            o0.x = acc[mt][nt][0] + bv.x;
            o0.y = acc[mt][nt][1] + bv.y;
            o1.x = acc[mt][nt][2] + bv.x;
            o1.y = acc[mt][nt][3] + bv.y;
            *(float2*)&C[(size_t)r * N + c]       = o0;
            *(float2*)&C[(size_t)(r + 8) * N + c] = o1;
        }
    }
}

// ============================================================================
// Tensor-core flash attention (ldmatrix, no online max, exp2 softmax).
// Q fragments pre-scaled by 0.125 * log2(e) so exp(s) == exp2(s_scaled):
// each softmax element costs one MUFU.EX2, no FMUL. Ratios (softmax) are
// identical; masked entries exp2(-huge) == 0.
// ============================================================================
#define AT_BM 64
#define AT_BN 64
#define ASTRD 68
#define AT_SMEM (3 * 64 * ASTRD * 4)   // 52224 B
#define QSCALE (0.125f * 1.44269504088896f)

__global__ void __launch_bounds__(128) attn_mma(
    const float* __restrict__ qkv, float* __restrict__ outp, int causal)
{
    extern __shared__ uint32_t asmem[];
    uint32_t* Ks = asmem;                  // [64][68]
    uint32_t* Vt = Ks + 64 * ASTRD;        // [64 d][68 key]
    uint32_t* Ps = Vt + 64 * ASTRD;        // [64][68]
    const uint32_t sK = smem_u32(Ks);
    const uint32_t sV = smem_u32(Vt);
    const uint32_t sP = smem_u32(Ps);

    const int b  = blockIdx.z;
    const int h  = blockIdx.y;
    const int m0 = (causal ? (gridDim.x - 1 - blockIdx.x) : blockIdx.x) * AT_BM;

    const int tid  = threadIdx.x;
    const int warp = tid >> 5;
    const int lane = tid & 31;
    const int lrow = lane >> 2;
    const int lcol = lane & 3;
    const int a_lrow = (lane & 15);
    const int a_lcol = (lane >> 4) << 2;
    const int b_lrow = (lane & 7) + ((lane >> 4) << 3);
    const int b_lcol = ((lane >> 3) & 1) << 2;

    const float* qbase = qkv + (size_t)b * T_SEQ * QKV_N + h * DH;
    const float* kbase = qbase + DIMC;
    const float* vbase = qbase + 2 * DIMC;

#pragma unroll
    for (int i = 0; i < 8; i++) {
        int idx = i * 128 + tid;
        int r = idx >> 4, c4 = (idx & 15) * 4;
        *(uint4*)&Ps[r * ASTRD + c4] =
            *(const uint4*)&qbase[(size_t)(m0 + r) * QKV_N + c4];
    }
    __syncthreads();

    uint32_t qa[8][4];
    {
        const float* Pf = (const float*)Ps;
        const int r0 = (warp * 16 + lrow) * ASTRD;
        const int r1 = r0 + 8 * ASTRD;
#pragma unroll
        for (int kt = 0; kt < 8; kt++) {
            int c = kt * 8 + lcol;
            qa[kt][0] = f32_to_tf32(Pf[r0 + c]     * QSCALE);
            qa[kt][1] = f32_to_tf32(Pf[r1 + c]     * QSCALE);
            qa[kt][2] = f32_to_tf32(Pf[r0 + c + 4] * QSCALE);
            qa[kt][3] = f32_to_tf32(Pf[r1 + c + 4] * QSCALE);
        }
    }
    __syncthreads();

    float o[8][4];
#pragma unroll
    for (int i = 0; i < 8; i++)
#pragma unroll
        for (int j = 0; j < 4; j++) o[i][j] = 0.0f;
    float l0 = 0.0f, l1 = 0.0f;

    const int r0g = m0 + warp * 16 + lrow;
    const int r1g = r0g + 8;

    const int n_start = causal ? 0 : m0;
    const int n_end   = causal ? (m0 + AT_BM) : T_SEQ;

    for (int n0 = n_start; n0 < n_end; n0 += AT_BN) {
#pragma unroll
        for (int i = 0; i < 8; i++) {
            int idx = i * 128 + tid;
            int r = idx >> 4, c4 = (idx & 15) * 4;
            *(uint4*)&Ks[r * ASTRD + c4] =
                *(const uint4*)&kbase[(size_t)(n0 + r) * QKV_N + c4];
        }
#pragma unroll
        for (int i = 0; i < 8; i++) {
            int idx = i * 128 + tid;
            int d  = idx & 63;
            int kg = idx >> 6;
            uint4 v;
            v.x = __float_as_uint(vbase[(size_t)(n0 + kg * 4 + 0) * QKV_N + d]);
            v.y = __float_as_uint(vbase[(size_t)(n0 + kg * 4 + 1) * QKV_N + d]);
            v.z = __float_as_uint(vbase[(size_t)(n0 + kg * 4 + 2) * QKV_N + d]);
            v.w = __float_as_uint(vbase[(size_t)(n0 + kg * 4 + 3) * QKV_N + d]);
            *(uint4*)&Vt[d * ASTRD + kg * 4] = v;
        }
        __syncthreads();

        // ---- S = Q K^T (scores already in log2 domain) ----
        float s[8][4];
#pragma unroll
        for (int nt = 0; nt < 8; nt++)
            s[nt][0] = s[nt][1] = s[nt][2] = s[nt][3] = 0.0f;
#pragma unroll
        for (int kt = 0; kt < 8; kt++) {
#pragma unroll
            for (int j = 0; j < 4; j++) {
                uint32_t b0, b1, b2, b3;
                uint32_t addr = sK +
                    (uint32_t)((j * 16 + b_lrow) * ASTRD + kt * 8 + b_lcol) * 4;
                ldsm_x4(b0, b1, b2, b3, addr);
                mma_tf32(s[2*j][0], s[2*j][1], s[2*j][2], s[2*j][3],
                         qa[kt][0], qa[kt][1], qa[kt][2], qa[kt][3], b0, b1);
                mma_tf32(s[2*j+1][0], s[2*j+1][1], s[2*j+1][2], s[2*j+1][3],
                         qa[kt][0], qa[kt][1], qa[kt][2], qa[kt][3], b2, b3);
            }
        }

        const bool need_mask = causal ? (n0 + AT_BN - 1 > m0 + warp * 16)
                                      : (n0 < m0 + warp * 16 + 15);
        if (need_mask) {
#pragma unroll
            for (int nt = 0; nt < 8; nt++) {
                int c0 = n0 + nt * 8 + 2 * lcol;
                int c1 = c0 + 1;
                if (causal) {
                    if (c0 > r0g) s[nt][0] = NEG_BIG;
                    if (c1 > r0g) s[nt][1] = NEG_BIG;
                    if (c0 > r1g) s[nt][2] = NEG_BIG;
                    if (c1 > r1g) s[nt][3] = NEG_BIG;
                } else {
                    if (c0 < r0g) s[nt][0] = NEG_BIG;
                    if (c1 < r0g) s[nt][1] = NEG_BIG;
                    if (c0 < r1g) s[nt][2] = NEG_BIG;
                    if (c1 < r1g) s[nt][3] = NEG_BIG;
                }
            }
        }

        // ---- exp2 + per-thread partial sums ----
#pragma unroll
        for (int nt = 0; nt < 8; nt++) {
            s[nt][0] = exp2f(s[nt][0]); l0 += s[nt][0];
            s[nt][1] = exp2f(s[nt][1]); l0 += s[nt][1];
            s[nt][2] = exp2f(s[nt][2]); l1 += s[nt][2];
            s[nt][3] = exp2f(s[nt][3]); l1 += s[nt][3];
        }

        // ---- P -> smem (warp-private rows, raw bits) ----
        {
            const int pr0 = (warp * 16 + lrow) * ASTRD;
            const int pr1 = pr0 + 8 * ASTRD;
#pragma unroll
            for (int nt = 0; nt < 8; nt++) {
                int c = nt * 8 + 2 * lcol;
                Ps[pr0 + c]     = __float_as_uint(s[nt][0]);
                Ps[pr0 + c + 1] = __float_as_uint(s[nt][1]);
                Ps[pr1 + c]     = __float_as_uint(s[nt][2]);
                Ps[pr1 + c + 1] = __float_as_uint(s[nt][3]);
            }
        }
        __syncwarp();

        // ---- O += P @ V ----
#pragma unroll
        for (int kt = 0; kt < 8; kt++) {
            uint32_t a0, a1, a2, a3;
            uint32_t aaddr = sP +
                (uint32_t)((warp * 16 + a_lrow) * ASTRD + kt * 8 + a_lcol) * 4;
            ldsm_x4(a0, a1, a2, a3, aaddr);
#pragma unroll
            for (int j = 0; j < 4; j++) {
                uint32_t b0, b1, b2, b3;
                uint32_t baddr = sV +
                    (uint32_t)((j * 16 + b_lrow) * ASTRD + kt * 8 + b_lcol) * 4;
                ldsm_x4(b0, b1, b2, b3, baddr);
                mma_tf32(o[2*j][0], o[2*j][1], o[2*j][2], o[2*j][3],
                         a0, a1, a2, a3, b0, b1);
                mma_tf32(o[2*j+1][0], o[2*j+1][1], o[2*j+1][2], o[2*j+1][3],
                         a0, a1, a2, a3, b2, b3);
            }
        }
        __syncthreads();
    }

    l0 += __shfl_xor_sync(0xffffffff, l0, 1);
    l0 += __shfl_xor_sync(0xffffffff, l0, 2);
    l1 += __shfl_xor_sync(0xffffffff, l1, 1);
    l1 += __shfl_xor_sync(0xffffffff, l1, 2);

    float inv0 = 1.0f / l0, inv1 = 1.0f / l1;
    size_t ob = (size_t)(b * T_SEQ + r0g) * DIMC + h * DH;
#pragma unroll
    for (int nt = 0; nt < 8; nt++) {
        int c = nt * 8 + 2 * lcol;
        float2 w0, w1;
        w0.x = o[nt][0] * inv0; w0.y = o[nt][1] * inv0;
        w1.x = o[nt][2] * inv1; w1.y = o[nt][3] * inv1;
        *(float2*)&outp[ob + c]            = w0;
        *(float2*)&outp[ob + 8 * DIMC + c] = w1;
    }
}

// ============================================================================
// Fused residual + LayerNorm, warp-shuffle reductions.
// ============================================================================
__global__ void residual_ln(const float* __restrict__ x,
                            const float* __restrict__ pc,
                            const float* __restrict__ pac,
                            const float* __restrict__ gamma,
                            const float* __restrict__ beta,
                            float* __restrict__ out)
{
    const int row = blockIdx.x;
    const size_t base = (size_t)row * DIMC;
    const int t = threadIdx.x;
    const int warp = t >> 5;
    const int lane = t & 31;

    __shared__ float red[8];

    float y[3];
    float s = 0.0f;
#pragma unroll
    for (int i = 0; i < 3; i++) {
        int c = t + i * 256;
        y[i] = x[base + c] + pc[base + c] + pac[base + c];
        s += y[i];
    }
#pragma unroll
    for (int off = 16; off > 0; off >>= 1)
        s += __shfl_xor_sync(0xffffffff, s, off);
    if (lane == 0) red[warp] = s;
    __syncthreads();
    float mu;
    {
        float v = red[lane & 7];
        v += __shfl_xor_sync(0xffffffff, v, 1);
        v += __shfl_xor_sync(0xffffffff, v, 2);
        v += __shfl_xor_sync(0xffffffff, v, 4);
        mu = v * (1.0f / DIMC);
    }

    float vs = 0.0f;
#pragma unroll
    for (int i = 0; i < 3; i++) {
        float d = y[i] - mu;
        vs += d * d;
    }
#pragma unroll
    for (int off = 16; off > 0; off >>= 1)
        vs += __shfl_xor_sync(0xffffffff, vs, off);
    __syncthreads();
    if (lane == 0) red[warp] = vs;
    __syncthreads();
    float inv;
    {
        float v = red[lane & 7];
        v += __shfl_xor_sync(0xffffffff, v, 1);
        v += __shfl_xor_sync(0xffffffff, v, 2);
        v += __shfl_xor_sync(0xffffffff, v, 4);
        inv = rsqrtf(v * (1.0f / DIMC) + 1e-5f);
    }

#pragma unroll
    for (int i = 0; i < 3; i++) {
        int c = t + i * 256;
        out[base + c] = (y[i] - mu) * inv * gamma[c] + beta[c];
    }
}

// ============================================================================
// launch — round-13 proven free-running two-stream fork/join
// ============================================================================
#define GEMM_SMEM(BM_T, BN_T) ((GSTG * ((BM_T) + (BN_T)) * RSTR) * 4)

extern "C" void kernel_launch(void* const* d_in, const int* in_sizes, int n_in,
                              void* d_out, int out_size)
{
    const float* x       = (const float*)d_in[0];
    const float* Wqkv_c  = (const float*)d_in[1];
    const float* bqkv_c  = (const float*)d_in[2];
    const float* Wp_c    = (const float*)d_in[3];
    const float* bp_c    = (const float*)d_in[4];
    const float* Wqkv_ac = (const float*)d_in[5];
    const float* bqkv_ac = (const float*)d_in[6];
    const float* Wp_ac   = (const float*)d_in[7];
    const float* bp_ac   = (const float*)d_in[8];
    const float* gamma   = (const float*)d_in[9];
    const float* beta    = (const float*)d_in[10];
    float* out = (float*)d_out;

    float *qkv_c, *qkv_ac, *attn_c, *attn_ac, *proj_c, *proj_ac;
    float *wtq_c, *wtq_ac, *wtp_c, *wtp_ac;
    cudaGetSymbolAddress((void**)&qkv_c,  g_qkv_c);
    cudaGetSymbolAddress((void**)&qkv_ac, g_qkv_ac);
    cudaGetSymbolAddress((void**)&attn_c,  g_attn_c);
    cudaGetSymbolAddress((void**)&attn_ac, g_attn_ac);
    cudaGetSymbolAddress((void**)&proj_c,  g_proj_c);
    cudaGetSymbolAddress((void**)&proj_ac, g_proj_ac);
    cudaGetSymbolAddress((void**)&wtq_c,  g_wtq_c);
    cudaGetSymbolAddress((void**)&wtq_ac, g_wtq_ac);
    cudaGetSymbolAddress((void**)&wtp_c,  g_wtp_c);
    cudaGetSymbolAddress((void**)&wtp_ac, g_wtp_ac);

    static cudaStream_t s1 = nullptr, s2 = nullptr;
    static cudaEvent_t ev0, ev1, ev2;
    if (!s1) {
        cudaStreamCreateWithFlags(&s1, cudaStreamNonBlocking);
        cudaStreamCreateWithFlags(&s2, cudaStreamNonBlocking);
        cudaEventCreateWithFlags(&ev0, cudaEventDisableTiming);
        cudaEventCreateWithFlags(&ev1, cudaEventDisableTiming);
        cudaEventCreateWithFlags(&ev2, cudaEventDisableTiming);
        cudaFuncSetAttribute((const void*)gemm_ldsm<128,128>,
                             cudaFuncAttributeMaxDynamicSharedMemorySize, GEMM_SMEM(128,128));
        cudaFuncSetAttribute((const void*)attn_mma,
                             cudaFuncAttributeMaxDynamicSharedMemorySize, AT_SMEM);
    }

    dim3 blk256(256);

    // ---- transposes on the capture stream (before fork) ----
    transpose_all<<<dim3(QKV_N / 32, KDIM / 32, 4), dim3(32, 8)>>>(
        Wqkv_c, wtq_c, Wqkv_ac, wtq_ac, Wp_c, wtp_c, Wp_ac, wtp_ac);

    // ---- fork ----
    cudaEventRecord(ev0, 0);
    cudaStreamWaitEvent(s1, ev0, 0);
    cudaStreamWaitEvent(s2, ev0, 0);

    // ---- branch c on s1 ----
    gemm_ldsm<128,128><<<dim3(QKV_N / 128, NROWS / 128, 1), blk256,
                         GEMM_SMEM(128,128), s1>>>(
        x, wtq_c, bqkv_c, qkv_c, NROWS, QKV_N, KDIM);
    attn_mma<<<dim3(T_SEQ / AT_BM, NH, B_SZ), dim3(128), AT_SMEM, s1>>>(
        qkv_c, attn_c, 1);
    gemm_ldsm<128,128><<<dim3(DIMC / 128, NROWS / 128, 1), blk256,
                         GEMM_SMEM(128,128), s1>>>(
        attn_c, wtp_c, bp_c, proj_c, NROWS, DIMC, KDIM);

    // ---- branch ac on s2 ----
    gemm_ldsm<128,128><<<dim3(QKV_N / 128, NROWS / 128, 1), blk256,
                         GEMM_SMEM(128,128), s2>>>(
        x, wtq_ac, bqkv_ac, qkv_ac, NROWS, QKV_N, KDIM);
    attn_mma<<<dim3(T_SEQ / AT_BM, NH, B_SZ), dim3(128), AT_SMEM, s2>>>(
        qkv_ac, attn_ac, 0);
    gemm_ldsm<128,128><<<dim3(DIMC / 128, NROWS / 128, 1), blk256,
                         GEMM_SMEM(128,128), s2>>>(
        attn_ac, wtp_ac, bp_ac, proj_ac, NROWS, DIMC, KDIM);

    // ---- join ----
    cudaEventRecord(ev1, s1);
    cudaEventRecord(ev2, s2);
    cudaStreamWaitEvent(0, ev1, 0);
    cudaStreamWaitEvent(0, ev2, 0);

    // ---- fused residual + layernorm ----
    residual_ln<<<NROWS, blk256>>>(x, proj_c, proj_ac, gamma, beta, out);
}